// round 15
// baseline (speedup 1.0000x reference)
#include <cuda_runtime.h>
#include <cstdint>

#define S_LEN 2048
#define BATCH 32
#define HID   256
#define NCOL  1024   // 4*H

// 256 MB scratch for Zx = x @ Wx + b.
// Layout: [s][b][jp], jp = r*128 + g*32 + m  -> per-CTA per-chain step slice is
// one contiguous 512B block (cp.async.bulk friendly).
__device__ float g_zx[(size_t)S_LEN * BATCH * NCOL];

// ----------------------------- helpers -----------------------------
__device__ __forceinline__ void fma2(unsigned long long &d, unsigned long long a, unsigned long long b) {
    asm("fma.rn.f32x2 %0, %1, %2, %0;" : "+l"(d) : "l"(a), "l"(b));
}
__device__ __forceinline__ unsigned long long pack2(float lo, float hi) {
    unsigned long long r; asm("mov.b64 %0, {%1, %2};" : "=l"(r) : "f"(lo), "f"(hi)); return r;
}
__device__ __forceinline__ float lo32(unsigned long long v){ return __uint_as_float((unsigned)(v & 0xffffffffull)); }
__device__ __forceinline__ float hi32(unsigned long long v){ return __uint_as_float((unsigned)(v >> 32)); }
__device__ __forceinline__ unsigned smem_u32(const void* p){ return (unsigned)__cvta_generic_to_shared(p); }
__device__ __forceinline__ unsigned mapa_rank(unsigned a, unsigned rk){
    unsigned r; asm("mapa.shared::cluster.u32 %0, %1, %2;" : "=r"(r) : "r"(a), "r"(rk)); return r;
}
__device__ __forceinline__ void cluster_sync_(){
    asm volatile("barrier.cluster.arrive.aligned;" ::: "memory");
    asm volatile("barrier.cluster.wait.aligned;" ::: "memory");
}
__device__ __forceinline__ float tanha(float x){
    float y; asm("tanh.approx.f32 %0, %1;" : "=f"(y) : "f"(x)); return y;
}

__device__ __forceinline__ void mbar_init(unsigned bar, unsigned cnt){
    asm volatile("mbarrier.init.shared.b64 [%0], %1;" :: "r"(bar), "r"(cnt) : "memory");
}
__device__ __forceinline__ void mbar_arm(unsigned bar, unsigned tx){
    asm volatile("mbarrier.arrive.expect_tx.shared.b64 _, [%0], %1;" :: "r"(bar), "r"(tx) : "memory");
}
__device__ __forceinline__ void mbar_wait(unsigned bar, unsigned parity){
    asm volatile(
        "{\n\t.reg .pred P;\n\t"
        "WL_%=:\n\t"
        "mbarrier.try_wait.parity.acquire.cluster.shared::cta.b64 P, [%0], %1, 0x989680;\n\t"
        "@!P bra WL_%=;\n\t}"
        :: "r"(bar), "r"(parity) : "memory");
}
// bulk global->shared with mbarrier tx-completion (UBLKCP)
__device__ __forceinline__ void bulk_g2s(unsigned dst, const void* src, unsigned bytes, unsigned bar){
    asm volatile("cp.async.bulk.shared::cluster.global.mbarrier::complete_tx::bytes [%0], [%1], %2, [%3];"
                 :: "r"(dst), "l"(src), "r"(bytes), "r"(bar) : "memory");
}
// bulk shared->shared (cross-CTA DSMEM) with remote mbarrier tx-completion
__device__ __forceinline__ void bulk_s2s(unsigned dst, unsigned src, unsigned bytes, unsigned rbar){
    asm volatile("cp.async.bulk.shared::cluster.shared::cta.mbarrier::complete_tx::bytes [%0], [%1], %2, [%3];"
                 :: "r"(dst), "r"(src), "r"(bytes), "r"(rbar) : "memory");
}
__device__ __forceinline__ void cp_async16(unsigned dst, const void* src){
    asm volatile("cp.async.cg.shared.global [%0], [%1], 16;" :: "r"(dst), "l"(src));
}
__device__ __forceinline__ void cp_commit(){ asm volatile("cp.async.commit_group;" ::: "memory"); }
__device__ __forceinline__ void cp_wait0(){ asm volatile("cp.async.wait_group 0;" ::: "memory"); }

__device__ __forceinline__ int jperm(int col){
    return ((col >> 5) & 7) * 128 + (col >> 8) * 32 + (col & 31);
}

__device__ __forceinline__ unsigned tf32_(float f){
    unsigned r; asm("cvt.rna.tf32.f32 %0, %1;" : "=r"(r) : "f"(f)); return r;
}
__device__ __forceinline__ void mma1688(float* d, const unsigned* a, unsigned b0, unsigned b1){
    asm("mma.sync.aligned.m16n8k8.row.col.f32.tf32.tf32.f32 "
        "{%0,%1,%2,%3}, {%4,%5,%6,%7}, {%8,%9}, {%0,%1,%2,%3};"
        : "+f"(d[0]), "+f"(d[1]), "+f"(d[2]), "+f"(d[3])
        : "r"(a[0]), "r"(a[1]), "r"(a[2]), "r"(a[3]), "r"(b0), "r"(b1));
}

// ----------------------------- phase 1: Zx = x @ Wx + b (tf32 tensor cores, unchanged) -----------------------------
__global__ void __launch_bounds__(256)
gemm_x_kernel(const float* __restrict__ x, const float* __restrict__ W, const float* __restrict__ bias,
              float* __restrict__ out, long long tail_start, long long tail_n)
{
    __shared__ float As[2][128][20];   // [buf][row][k]
    __shared__ float Bs[2][16][136];   // [buf][k][col]

    const int tid = threadIdx.x;

    if (blockIdx.x == 0 && blockIdx.y < 64) {
        long long i = (long long)blockIdx.y * 256 + tid;
        if (i < tail_n) out[tail_start + i] = 0.0f;
    }

    const int colTile = blockIdx.x * 128;
    const int rowTile = blockIdx.y * 128;

    const int wid = tid >> 5, lane = tid & 31;
    const int wm = wid & 3;
    const int wn = wid >> 2;
    const int gid = lane >> 2;
    const int tig = lane & 3;

    float d[2][8][4];
    #pragma unroll
    for (int f = 0; f < 2; f++)
        #pragma unroll
        for (int j = 0; j < 8; j++)
            #pragma unroll
            for (int q = 0; q < 4; q++) d[f][j][q] = 0.0f;

    auto loadA = [&](int k0, int buf){
        #pragma unroll
        for (int j = 0; j < 2; j++){
            int i = tid * 2 + j;
            int row = i >> 2, seg = i & 3;
            int rr = rowTile + row;
            int bb = rr & 31, ss = rr >> 5;
            cp_async16(smem_u32(&As[buf][row][seg * 4]),
                       &x[((size_t)bb * S_LEN + ss) * 256 + k0 + seg * 4]);
        }
    };
    auto loadB = [&](int k0, int buf){
        #pragma unroll
        for (int j = 0; j < 2; j++){
            int i = tid * 2 + j;
            int k = i >> 5, seg = i & 31;
            cp_async16(smem_u32(&Bs[buf][k][seg * 4]),
                       &W[(size_t)(k0 + k) * NCOL + colTile + seg * 4]);
        }
    };

    loadA(0, 0); loadB(0, 0); cp_commit();
    cp_wait0();
    __syncthreads();

    int cur = 0;
    for (int chunk = 0; chunk < 16; chunk++){
        if (chunk < 15){
            loadA((chunk + 1) * 16, cur ^ 1);
            loadB((chunk + 1) * 16, cur ^ 1);
            cp_commit();
        }

        #pragma unroll
        for (int kb = 0; kb < 2; kb++){
            unsigned a[2][4];
            #pragma unroll
            for (int f = 0; f < 2; f++){
                int r0 = wm * 32 + f * 16 + gid;
                a[f][0] = tf32_(As[cur][r0][kb * 8 + tig]);
                a[f][1] = tf32_(As[cur][r0 + 8][kb * 8 + tig]);
                a[f][2] = tf32_(As[cur][r0][kb * 8 + tig + 4]);
                a[f][3] = tf32_(As[cur][r0 + 8][kb * 8 + tig + 4]);
            }
            #pragma unroll
            for (int j = 0; j < 8; j++){
                int c = wn * 64 + j * 8 + gid;
                unsigned b0 = tf32_(Bs[cur][kb * 8 + tig][c]);
                unsigned b1 = tf32_(Bs[cur][kb * 8 + tig + 4][c]);
                mma1688(d[0][j], a[0], b0, b1);
                mma1688(d[1][j], a[1], b0, b1);
            }
        }

        if (chunk < 15){
            cp_wait0();
            __syncthreads();
            cur ^= 1;
        }
    }

    #pragma unroll
    for (int j = 0; j < 8; j++){
        int c = colTile + wn * 64 + j * 8 + tig * 2;
        float bv0 = bias[c], bv1 = bias[c + 1];
        int jp = jperm(c);
        #pragma unroll
        for (int f = 0; f < 2; f++){
            int r0 = rowTile + wm * 32 + f * 16 + gid;
            float2 lo = { d[f][j][0] + bv0, d[f][j][1] + bv1 };
            float2 hi = { d[f][j][2] + bv0, d[f][j][3] + bv1 };
            *(float2*)&g_zx[(size_t)r0 * NCOL + jp]       = lo;
            *(float2*)&g_zx[(size_t)(r0 + 8) * NCOL + jp] = hi;
        }
    }
}

// ----------------------------- phase 2: the recurrence -----------------------------
// Exchange rebuilt as BULK DSMEM: owners stage 4 h-values/warp into a 256B
// local buffer (2 STS.64), one __syncthreads, then warp 15 lanes 0-7 each send
// ONE cp.async.bulk (256B) to a peer's rx slot, completing on the peer's
// ping-pong mbarrier. Arrivals per barrier per step: 10 (8 h-bulks + 2 zx)
// instead of 258 -> kills mbarrier tx-update serialization.
// rx[par][rk] has a 68-float stride so every LDS.128 phase of the FMA loop is
// bank-conflict-free without a repack step.
__global__ void __cluster_dims__(8, 1, 1) __launch_bounds__(512, 1)
lstm_chain_kernel(const float* __restrict__ W, const float* __restrict__ h0,
                  const float* __restrict__ c0, float* __restrict__ out)
{
    __shared__ __align__(16) float rx[2][8][68];     // [parity][src rank][ch0:32|ch1:32|pad:4]
    __shared__ __align__(16) float stage[2][64];     // [parity][ch0:32|ch1:32]
    __shared__ __align__(16) float zx_s[4][2][128];  // [slot][chain][g*32+m]
    __shared__ __align__(8) unsigned long long mbar[2];

    const int tid  = threadIdx.x;
    const int p    = blockIdx.x >> 3;
    const int r    = blockIdx.x & 7;
    const int lane = tid & 31;

    const int m  = tid >> 4;     // 0..31 unit (local)
    const int ks = tid & 15;     // k-slice

    // ---- weights: w2[g*8+q] covers k = ks*16 + 2q,2q+1, col = g*256 + r*32 + m
    unsigned long long w2[32];
    {
        const float* Wb = W + (size_t)(256 + ks * 16) * NCOL + r * 32 + m;
        #pragma unroll
        for (int g = 0; g < 4; g++)
            #pragma unroll
            for (int q = 0; q < 8; q++)
                w2[g * 8 + q] = pack2(Wb[(size_t)(2 * q) * NCOL + g * 256],
                                      Wb[(size_t)(2 * q + 1) * NCOL + g * 256]);
    }

    const unsigned rx_base  = smem_u32(&rx[0][0][0]);
    const unsigned stg_base = smem_u32(&stage[0][0]);
    const unsigned mb_base  = smem_u32(&mbar[0]);

    const float* zx_src = g_zx + (size_t)(2 * p) * NCOL + r * 128;
    const size_t zx_step = (size_t)BATCH * NCOL;

    if (tid == 511) {
        mbar_init(mb_base, 1);
        mbar_init(mb_base + 8, 1);
        mbar_arm(mb_base, 3072);      // waited at s=2: h(s=1) 8x256 + zx(s=2) 2x512
        mbar_arm(mb_base + 8, 3072);  // waited at s=1: h(s=0) + zx(s=1)
        bulk_g2s(smem_u32(&zx_s[1][0][0]), zx_src + 1 * zx_step,        512, mb_base + 8);
        bulk_g2s(smem_u32(&zx_s[1][1][0]), zx_src + 1 * zx_step + NCOL, 512, mb_base + 8);
    }

    // ---- init rx[0] with h0 (full h, both chains, local copy per CTA)
    {
        int ch = tid >> 8, k = tid & 255;
        rx[0][k >> 5][ch * 32 + (k & 31)] = h0[(size_t)(2 * p + ch) * HID + k];
    }

    // ---- lane roles from v = ks&7
    const int v_ch   = (ks >> 2) & 1;
    const int v_gate = ks & 3;
    const bool owner = (v_gate == 1) && (ks < 8);

    float cst = 0.0f;
    if (v_gate == 1) cst = c0[(size_t)(2 * p + v_ch) * HID + r * 32 + m];

    float zx0v = __ldg(zx_src + (size_t)v_ch * NCOL + v_gate * 32 + m);

    // peer addresses for the 8 bulk sends (warp 15 lanes 0-7 use lane as rank)
    const int m0 = 2 * (tid >> 5);             // even unit of this warp
    unsigned peer_rx = 0, peer_mb = 0;
    if ((tid >> 5) == 15 && lane < 8) {
        peer_rx = mapa_rank(rx_base, lane) + (unsigned)(r * 272);   // + parN*2176 later
        peer_mb = mapa_rank(mb_base, lane);                          // + parN*8 later
    }

    float* out_ptr = out + ((size_t)(2 * p + v_ch) * S_LEN) * HID + r * 32 + m;

    // h-gather roles (same as R13/14): lanes<8 get chain0 pair, 16-23 chain1
    const int  s_ch = (lane < 8) ? 0 : 1;
    const int  srcA = s_ch ? 5 : 1;            // hn lanes: even unit
    const int  srcB = srcA + 16;               // odd unit

    const bool b0 = (ks & 1), b1 = (ks >> 1) & 1, b2 = (ks >> 2) & 1;

    __syncthreads();
    cluster_sync_();   // barriers armed + rx[0] ready cluster-wide

    int ph0 = 0, ph1 = 0;

    for (int s = 0; s < S_LEN; s++) {
        const int par = s & 1;
        const int parN = par ^ 1;

        if (s > 0) {
            unsigned bar = mb_base + (unsigned)par * 8;
            int ph = par ? ph1 : ph0;
            mbar_wait(bar, (unsigned)ph);      // all warps sleep; per-warp acquire
            if (par) ph1 ^= 1; else ph0 ^= 1;
            if (tid == 511) {
                mbar_arm(bar, 3072);           // phase used at s+2
                if (s + 2 < S_LEN) {
                    const int slot = (s + 2) & 3;
                    const float* src = zx_src + (size_t)(s + 2) * zx_step;
                    bulk_g2s(smem_u32(&zx_s[slot][0][0]), src,        512, bar);
                    bulk_g2s(smem_u32(&zx_s[slot][1][0]), src + NCOL, 512, bar);
                }
            }
        } else {
            if (tid == 511) {
                bulk_g2s(smem_u32(&zx_s[2][0][0]), zx_src + 2 * zx_step,        512, mb_base);
                bulk_g2s(smem_u32(&zx_s[2][1][0]), zx_src + 2 * zx_step + NCOL, 512, mb_base);
            }
        }

        // ---- Wh . h over this thread's 16-k slice (reads rx directly)
        unsigned long long accA[4] = {0,0,0,0}, accB[4] = {0,0,0,0};
        const float* hb = &rx[par][ks >> 1][(ks & 1) * 16];
        {
            const ulonglong2* h2 = (const ulonglong2*)hb;           // chain 0
            ulonglong2 q0 = h2[0], q1 = h2[1], q2 = h2[2], q3 = h2[3];
            unsigned long long h8[8] = {q0.x, q0.y, q1.x, q1.y, q2.x, q2.y, q3.x, q3.y};
            #pragma unroll
            for (int g = 0; g < 4; g++)
                #pragma unroll
                for (int q = 0; q < 8; q++) fma2(accA[g], w2[g * 8 + q], h8[q]);
        }
        {
            const ulonglong2* h2 = (const ulonglong2*)(hb + 32);    // chain 1
            ulonglong2 q0 = h2[0], q1 = h2[1], q2 = h2[2], q3 = h2[3];
            unsigned long long h8[8] = {q0.x, q0.y, q1.x, q1.y, q2.x, q2.y, q3.x, q3.y};
            #pragma unroll
            for (int g = 0; g < 4; g++)
                #pragma unroll
                for (int q = 0; q < 8; q++) fma2(accB[g], w2[g * 8 + q], h8[q]);
        }

        float sv[8];
        #pragma unroll
        for (int g = 0; g < 4; g++) {
            sv[g]     = lo32(accA[g]) + hi32(accA[g]);
            sv[4 + g] = lo32(accB[g]) + hi32(accB[g]);
        }

        // ---- value-splitting butterfly (8 shfls); lane ks ends with v=ks&7
        float k0v[4], k1v[2], k2v;
        #pragma unroll
        for (int j = 0; j < 4; j++) {
            float snd = b0 ? sv[2 * j] : sv[2 * j + 1];
            float rcv = __shfl_xor_sync(0xffffffffu, snd, 1);
            k0v[j] = (b0 ? sv[2 * j + 1] : sv[2 * j]) + rcv;
        }
        #pragma unroll
        for (int j = 0; j < 2; j++) {
            float snd = b1 ? k0v[2 * j] : k0v[2 * j + 1];
            float rcv = __shfl_xor_sync(0xffffffffu, snd, 2);
            k1v[j] = (b1 ? k0v[2 * j + 1] : k0v[2 * j]) + rcv;
        }
        {
            float snd = b2 ? k1v[0] : k1v[1];
            float rcv = __shfl_xor_sync(0xffffffffu, snd, 4);
            k2v = (b2 ? k1v[1] : k1v[0]) + rcv;
        }
        float F = k2v + __shfl_xor_sync(0xffffffffu, k2v, 8);

        // ---- distributed tail
        float zx = (s == 0) ? zx0v : zx_s[s & 3][v_ch][v_gate * 32 + m];
        float t = tanha(F + zx);
        float u = (v_gate == 2) ? t : 0.5f * t;
        float w = tanha(u);
        float a = (v_gate == 2) ? w : fmaf(0.5f, w, 0.5f);

        float ax = __shfl_xor_sync(0xffffffffu, a, 2);
        float P  = a * ax;
        float Pr = __shfl_xor_sync(0xffffffffu, P, 1);

        float hn = 0.0f;
        if (v_gate == 1) {
            cst = a * cst + Pr;
            hn  = tanha(cst) * ax;
        }

        // gather unit-pair hn (hn lives at lanes 1/5/17/21)
        float hA = __shfl_sync(0xffffffffu, hn, srcA);
        float hB = __shfl_sync(0xffffffffu, hn, srcB);

        // stage this warp's 4 h values (2 STS.64 by lanes 0 and 16)
        if (lane == 0 || lane == 16)
            *(unsigned long long*)&stage[parN][s_ch * 32 + m0] = pack2(hA, hB);

        if (owner)
            out_ptr[0] = hn;
        out_ptr += HID;

        if (s + 1 < S_LEN) {
            __syncthreads();               // staging complete across all warps
            if ((tid >> 5) == 15 && lane < 8)
                bulk_s2s(peer_rx + (unsigned)(parN * 2176),
                         stg_base + (unsigned)(parN * 256),
                         256,
                         peer_mb + (unsigned)(parN * 8));
        }
    }

    cluster_sync_();   // no CTA exits while remote bulk traffic may be in flight
}

// ----------------------------- launcher -----------------------------
extern "C" void kernel_launch(void* const* d_in, const int* in_sizes, int n_in,
                              void* d_out, int out_size) {
    const float* x    = (const float*)d_in[0];   // (32, 2048, 256)
    const float* h0   = (const float*)d_in[1];   // (1, 32, 256)
    const float* c0   = (const float*)d_in[2];   // (1, 32, 256)
    const float* W    = (const float*)d_in[3];   // (512, 1024)
    const float* bias = (const float*)d_in[4];   // (1024,)
    float* out = (float*)d_out;

    const long long main_elems = (long long)BATCH * S_LEN * HID;
    const long long tail = (long long)out_size - main_elems;

    gemm_x_kernel<<<dim3(8, 512, 1), 256>>>(x, W, bias, out, main_elems, tail > 0 ? tail : 0);
    lstm_chain_kernel<<<128, 512>>>(W, h0, c0, out);
}